// round 1
// baseline (speedup 1.0000x reference)
#include <cuda_runtime.h>
#include <math.h>

// Problem constants (fixed by setup_inputs)
#define LMAXC 180
#define LC    181           // L = lmax+1
#define MMC   361           // 2*lmax+1
#define FC    50            // n_freqs
#define NCC   100           // 2*F real columns (re/im interleaved)
#define NCPC  104           // padded smem width
#define TMC   32            // m-tile
#define KCC   32            // k-chunk
#define NTHREADS 128
#define SIDEREALF 6.3003880989848976f   // 2*pi*1.00273790935 (fp32 of double)
#define SQRT4PI   3.5449077018110318f

// Scratch (no allocations allowed): S[m][2f] accumulator + per-freq norm
__device__ float g_S[MMC * NCC];
__device__ float g_norm[FC];

__global__ void zero_S() {
    int i = blockIdx.x * blockDim.x + threadIdx.x;
    if (i < MMC * NCC) g_S[i] = 0.0f;
}

// Per (l, m-tile) CTA:
//   D[m,f] = sum_n dl[l,m,n] * conj(beam[f,l,n]*pg[n])     (real GEMM, 2F cols)
//   S[m,f] += conj(pa[m]) * D[m,f] * sky[f,l,m]            (valid (l,m) only)
// l==0 CTA also writes g_norm[f] = sqrt(4pi)*Re(D[m=0,f]).
__global__ void __launch_bounds__(NTHREADS) conv_kernel(
    const float* __restrict__ br_g, const float* __restrict__ bi_g,
    const float* __restrict__ sr_g, const float* __restrict__ si_g,
    const float* __restrict__ dl_g, const float* __restrict__ euler)
{
    const int l  = blockIdx.y;
    const int j0 = LMAXC - l, j1 = LMAXC + l;
    const int ntiles = (2 * l + 1 + TMC - 1) / TMC;
    const int mt = blockIdx.x;
    if (mt >= ntiles) return;
    const int jm0 = j0 + mt * TMC;

    const float alpha = euler[0];
    const float gamma = euler[2];

    __shared__ float a_sm[TMC][KCC + 1];
    __shared__ float b_sm[KCC][NCPC];
    __shared__ float pgc[KCC], pgs[KCC];

    const int tid = threadIdx.x;
    const int r   = tid >> 2;      // 32 m-rows
    const int cg  = tid & 3;       // 4 column groups
    const int cbase = cg * 26;     // 26 cols per thread (cols 100..103 are padding)

    float acc[26];
    #pragma unroll
    for (int c = 0; c < 26; c++) acc[c] = 0.0f;

    for (int k0 = j0; k0 <= j1; k0 += KCC) {
        __syncthreads();  // previous compute done before overwriting tiles

        // dl tile: rows jm0..jm0+31, cols k0..k0+31 (coalesced 128B rows)
        for (int i = tid; i < TMC * KCC; i += NTHREADS) {
            int rr = i >> 5, cc = i & 31;
            int jj = jm0 + rr, nn = k0 + cc;
            float v = 0.0f;
            if (jj <= j1 && nn <= j1)
                v = dl_g[((size_t)l * MMC + jj) * MMC + nn];
            a_sm[rr][cc] = v;
        }
        // pg phases for this k-chunk
        if (tid < KCC) {
            int nn = k0 + tid;
            float s = 0.0f, c = 0.0f;
            if (nn <= j1) sincosf((float)(nn - LMAXC) * gamma, &s, &c);
            pgc[tid] = c; pgs[tid] = s;
        }
        __syncthreads();

        // B tile: conj(beam * pg), re/im as separate columns
        for (int i = tid; i < KCC * FC; i += NTHREADS) {
            int nl = i & 31, f = i >> 5;
            int nn = k0 + nl;
            float brv = 0.0f, biv = 0.0f;
            if (nn <= j1) {
                size_t off = ((size_t)f * LC + l) * MMC + nn;
                brv = br_g[off]; biv = bi_g[off];
            }
            float c = pgc[nl], s = pgs[nl];
            b_sm[nl][2 * f]     = brv * c + biv * s;   // Re(conj(beam*pg))
            b_sm[nl][2 * f + 1] = brv * s - biv * c;   // Im(conj(beam*pg))
        }
        if (tid < KCC) {  // zero the padding columns read by cg==3
            b_sm[tid][100] = 0.f; b_sm[tid][101] = 0.f;
            b_sm[tid][102] = 0.f; b_sm[tid][103] = 0.f;
        }
        __syncthreads();

        const int kmax = min(KCC, j1 - k0 + 1);
        for (int k = 0; k < kmax; k++) {
            float a = a_sm[r][k];
            const float2* bp = reinterpret_cast<const float2*>(&b_sm[k][cbase]);
            #pragma unroll
            for (int c2 = 0; c2 < 13; c2++) {
                float2 b = bp[c2];
                acc[2 * c2]     += a * b.x;
                acc[2 * c2 + 1] += a * b.y;
            }
        }
    }

    const int jrow = jm0 + r;
    if (jrow <= j1) {
        float sa, ca;  // conj(pa[m]) = exp(+i m alpha)
        sincosf((float)(jrow - LMAXC) * alpha, &sa, &ca);
        #pragma unroll
        for (int p = 0; p < 13; p++) {
            int f = cg * 13 + p;
            if (f < FC) {
                float dre = acc[2 * p], dim = acc[2 * p + 1];
                float z1r = ca * dre - sa * dim;
                float z1i = ca * dim + sa * dre;
                size_t soff = ((size_t)f * LC + l) * MMC + jrow;
                float skr = sr_g[soff], ski = si_g[soff];
                atomicAdd(&g_S[jrow * NCC + 2 * f],     z1r * skr - z1i * ski);
                atomicAdd(&g_S[jrow * NCC + 2 * f + 1], z1r * ski + z1i * skr);
            }
        }
        if (l == 0) {   // jrow==LMAXC here; pa[0]=1, Re(D)=Re(beam_eq[f,0,0])
            #pragma unroll
            for (int p = 0; p < 13; p++) {
                int f = cg * 13 + p;
                if (f < FC) g_norm[f] = SQRT4PI * acc[2 * p];
            }
        }
    }
}

// Per-time block: build e^{i m phi_t} table, contract with S, normalize, ground mix.
__global__ void vis_kernel(const float* __restrict__ times,
                           const float* __restrict__ fsky,
                           const float* __restrict__ tg,
                           float* __restrict__ out)
{
    const int t = blockIdx.x;
    __shared__ float phc[MMC], phs[MMC];
    float phi = SIDEREALF * times[t];
    for (int j = threadIdx.x; j < MMC; j += blockDim.x) {
        float s, c;
        sincosf((float)(j - LMAXC) * phi, &s, &c);
        phc[j] = c; phs[j] = s;
    }
    __syncthreads();
    int f = threadIdx.x;
    if (f < FC) {
        float acc = 0.0f;
        #pragma unroll 4
        for (int j = 0; j < MMC; j++) {
            acc += phc[j] * g_S[j * NCC + 2 * f]
                 - phs[j] * g_S[j * NCC + 2 * f + 1];
        }
        float v  = acc / g_norm[f];
        float fs = fsky[f];
        out[t * FC + f] = fs * v + (1.0f - fs) * 300.0f * tg[0];
    }
}

extern "C" void kernel_launch(void* const* d_in, const int* in_sizes, int n_in,
                              void* d_out, int out_size)
{
    const float* br    = (const float*)d_in[0];
    const float* bi    = (const float*)d_in[1];
    const float* sr    = (const float*)d_in[2];
    const float* si    = (const float*)d_in[3];
    const float* dl    = (const float*)d_in[4];
    const float* euler = (const float*)d_in[5];
    const float* times = (const float*)d_in[6];
    const float* fsky  = (const float*)d_in[7];
    const float* tg    = (const float*)d_in[8];
    float* out = (float*)d_out;
    const int T = in_sizes[6];

    zero_S<<<(MMC * NCC + 255) / 256, 256>>>();

    dim3 grid((MMC + TMC - 1) / TMC, LC);
    conv_kernel<<<grid, NTHREADS>>>(br, bi, sr, si, dl, euler);

    vis_kernel<<<T, 128>>>(times, fsky, tg, out);
}